// round 7
// baseline (speedup 1.0000x reference)
#include <cuda_runtime.h>
#include <stdint.h>

// ParallelTransport: out[e, c, :] = R(rho[e]) @ x[row[e], c, :]
// x: (1, N, 32, 2) fp32 ; edge_index: (2, E) int32 ; rho: (E,) fp32
// out: (1, E, 32, 2) fp32
//
// R7: persistent grid-stride version of the R3/R6 kernel. 16 thr/edge,
// one float4 per thread, ITER=4 batched phases (MLP~4 on the L2 gather),
// streaming stores. Grid sized to exactly fill 148 SMs x 8 CTAs; each CTA
// loops over chunks of TPB*ITER slots, check-free (tail kernel covers
// any non-multiple remainder).

#define ITER 4
#define TPB  256
#define CHUNK (TPB * ITER)

__global__ void __launch_bounds__(TPB)
pt_kernel(const float* __restrict__ x,
          const int* __restrict__ row,
          const float* __restrict__ rho,
          float4* __restrict__ out,
          unsigned nchunks)
{
    for (unsigned chunk = blockIdx.x; chunk < nchunks; chunk += gridDim.x) {
        unsigned base = chunk * CHUNK + threadIdx.x;

        int    r[ITER];
        float  rv[ITER];
        float4 v[ITER];

        // Phase 1: index + rho loads (L1-broadcast within 16-lane groups)
        #pragma unroll
        for (int i = 0; i < ITER; i++) {
            unsigned e = (base + i * TPB) >> 4;
            r[i]  = __ldg(&row[e]);
            rv[i] = __ldg(&rho[e]);
        }

        // Phase 2: dependent gathers — 4 independent chains in flight
        #pragma unroll
        for (int i = 0; i < ITER; i++) {
            unsigned sub = (base + i * TPB) & 15u;
            v[i] = __ldg(reinterpret_cast<const float4*>(x)
                         + ((unsigned)r[i] * 16u + sub));
        }

        // Phase 3: rotate + streaming store
        #pragma unroll
        for (int i = 0; i < ITER; i++) {
            float s, c;
            __sincosf(rv[i], &s, &c);
            float4 o;
            o.x = fmaf(c, v[i].x, -s * v[i].y);
            o.y = fmaf(s, v[i].x,  c * v[i].y);
            o.z = fmaf(c, v[i].z, -s * v[i].w);
            o.w = fmaf(s, v[i].z,  c * v[i].w);
            __stcs(&out[base + i * TPB], o);
        }
    }
}

// Tail: handles slots [start, total) if total % CHUNK != 0 (empty for E=1.6M)
__global__ void __launch_bounds__(TPB)
pt_tail_kernel(const float* __restrict__ x,
               const int* __restrict__ row,
               const float* __restrict__ rho,
               float4* __restrict__ out,
               unsigned start, unsigned total)
{
    unsigned slot = start + blockIdx.x * TPB + threadIdx.x;
    if (slot >= total) return;
    unsigned e = slot >> 4, sub = slot & 15u;
    int   r  = __ldg(&row[e]);
    float rv = __ldg(&rho[e]);
    float s, c;
    __sincosf(rv, &s, &c);
    float4 v = __ldg(reinterpret_cast<const float4*>(x) + ((unsigned)r * 16u + sub));
    float4 o;
    o.x = fmaf(c, v.x, -s * v.y);
    o.y = fmaf(s, v.x,  c * v.y);
    o.z = fmaf(c, v.z, -s * v.w);
    o.w = fmaf(s, v.z,  c * v.w);
    __stcs(&out[slot], o);
}

extern "C" void kernel_launch(void* const* d_in, const int* in_sizes, int n_in,
                              void* d_out, int out_size)
{
    const float* x    = (const float*)d_in[0];
    const int*   eidx = (const int*)d_in[1];   // (2, E): first E entries = row
    const float* rho  = (const float*)d_in[2];

    unsigned E = (unsigned)in_sizes[2];
    unsigned total   = E * 16u;                // float4 slots
    unsigned nchunks = total / CHUNK;
    unsigned covered = nchunks * CHUNK;

    // Exactly fill the chip: 148 SMs x 8 CTAs of 256 thr @ 32 regs
    unsigned grid = 148u * 8u;
    if (grid > nchunks) grid = nchunks ? nchunks : 1;

    if (nchunks)
        pt_kernel<<<grid, TPB>>>(x, eidx, rho, (float4*)d_out, nchunks);

    if (covered < total) {
        unsigned rem = total - covered;
        unsigned tb  = (rem + TPB - 1) / TPB;
        pt_tail_kernel<<<tb, TPB>>>(x, eidx, rho, (float4*)d_out, covered, total);
    }
}